// round 8
// baseline (speedup 1.0000x reference)
#include <cuda_runtime.h>
#include <cuda_bf16.h>

// BioTripletLoss: B=16384 rows, D=1024 fp32.
// pos = ||h+r-t||, neg = ||h+r-t[neg_idx]||
// dissim (rel==1): relu(0.6 - pos) + 0.5*exp(-pos)
// sim:             relu(pos - neg + 0.3) + 0.3*relu(0.1 - pos)
// out = mean over B.
//
// R8 = R7 (best shape: 2 rows/CTA, front-batched plain-global cache_hint
// loads, one atomic per CTA, regs 30, occ 90%) with the zero_out kernel
// replaced by a last-CTA-finalize protocol: device-global scratch + ticket
// counter; the final CTA writes out[0] and resets state for the next graph
// replay. One kernel launch per replay instead of two.
// L2 policy: h, r -> evict_first (single-use); t -> evict_last (gather reuse).

#define DDIM 1024
#define NTHREADS 256
#define ROWS_PER_CTA 2

static constexpr float MARGIN = 0.3f;
static constexpr float MIN_POS_DIST = 0.1f;
static constexpr float PUSH_SCALE = 2.0f;

__device__ float g_scratch = 0.0f;          // running sum of per-sample losses
__device__ unsigned int g_ticket = 0u;      // CTA completion counter

// Plain global-path 128-bit load with L2 eviction policy (no .nc).
__device__ __forceinline__ float4 ld_hint4(const float4* p, unsigned long long pol) {
    float4 v;
    asm("ld.global.L2::cache_hint.v4.f32 {%0,%1,%2,%3}, [%4], %5;"
        : "=f"(v.x), "=f"(v.y), "=f"(v.z), "=f"(v.w)
        : "l"(p), "l"(pol));
    return v;
}

__device__ __forceinline__ float per_sample_loss(float ps, float ns, int rel) {
    float pos_dist = sqrtf(ps);
    float neg_dist = sqrtf(ns);
    float loss;
    if (rel == 1) {
        loss = fmaxf(MARGIN * PUSH_SCALE - pos_dist, 0.0f) + 0.5f * expf(-pos_dist);
    } else {
        loss = fmaxf(pos_dist - neg_dist + MARGIN, 0.0f)
             + 0.3f * fmaxf(MIN_POS_DIST - pos_dist, 0.0f);
    }
    return loss;
}

__global__ __launch_bounds__(NTHREADS)
void triplet_loss_kernel(const float* __restrict__ h,
                         const float* __restrict__ t,
                         const float* __restrict__ r,
                         const int* __restrict__ relation_ids,
                         const int* __restrict__ neg_idx,
                         float* __restrict__ out,
                         int B) {
    const int row0 = blockIdx.x * ROWS_PER_CTA;
    const int row1 = row0 + 1;
    const int tid = threadIdx.x;

    unsigned long long pol_first, pol_last;
    asm("createpolicy.fractional.L2::evict_first.b64 %0, 1.0;" : "=l"(pol_first));
    asm("createpolicy.fractional.L2::evict_last.b64 %0, 1.0;"  : "=l"(pol_last));

    const int j0 = __ldg(&neg_idx[row0]);
    const int j1 = __ldg(&neg_idx[row1]);

    const float4* __restrict__ h4 = reinterpret_cast<const float4*>(h);
    const float4* __restrict__ r4 = reinterpret_cast<const float4*>(r);
    const float4* __restrict__ t4 = reinterpret_cast<const float4*>(t);
    const int V = DDIM / 4;  // 256 float4 per row == one per thread

    // Front-batch all 8 loads (MLP = 8).
    float4 hv0 = ld_hint4(h4 + (size_t)row0 * V + tid, pol_first);
    float4 rv0 = ld_hint4(r4 + (size_t)row0 * V + tid, pol_first);
    float4 tv0 = ld_hint4(t4 + (size_t)row0 * V + tid, pol_last);
    float4 nv0 = ld_hint4(t4 + (size_t)j0   * V + tid, pol_last);
    float4 hv1 = ld_hint4(h4 + (size_t)row1 * V + tid, pol_first);
    float4 rv1 = ld_hint4(r4 + (size_t)row1 * V + tid, pol_first);
    float4 tv1 = ld_hint4(t4 + (size_t)row1 * V + tid, pol_last);
    float4 nv1 = ld_hint4(t4 + (size_t)j1   * V + tid, pol_last);

    float hx, hy, hz, hw, d;

    // Row 0
    hx = hv0.x + rv0.x; hy = hv0.y + rv0.y; hz = hv0.z + rv0.z; hw = hv0.w + rv0.w;
    float ps0 = 0.0f, ns0 = 0.0f;
    d = hx - tv0.x; ps0 += d*d;  d = hy - tv0.y; ps0 += d*d;
    d = hz - tv0.z; ps0 += d*d;  d = hw - tv0.w; ps0 += d*d;
    d = hx - nv0.x; ns0 += d*d;  d = hy - nv0.y; ns0 += d*d;
    d = hz - nv0.z; ns0 += d*d;  d = hw - nv0.w; ns0 += d*d;

    // Row 1
    hx = hv1.x + rv1.x; hy = hv1.y + rv1.y; hz = hv1.z + rv1.z; hw = hv1.w + rv1.w;
    float ps1 = 0.0f, ns1 = 0.0f;
    d = hx - tv1.x; ps1 += d*d;  d = hy - tv1.y; ps1 += d*d;
    d = hz - tv1.z; ps1 += d*d;  d = hw - tv1.w; ps1 += d*d;
    d = hx - nv1.x; ns1 += d*d;  d = hy - nv1.y; ns1 += d*d;
    d = hz - nv1.z; ns1 += d*d;  d = hw - nv1.w; ns1 += d*d;

    // Warp reduce all four accumulators
    #pragma unroll
    for (int off = 16; off > 0; off >>= 1) {
        ps0 += __shfl_xor_sync(0xFFFFFFFFu, ps0, off);
        ns0 += __shfl_xor_sync(0xFFFFFFFFu, ns0, off);
        ps1 += __shfl_xor_sync(0xFFFFFFFFu, ps1, off);
        ns1 += __shfl_xor_sync(0xFFFFFFFFu, ns1, off);
    }

    // Block reduce across 8 warps
    __shared__ float s_ps0[NTHREADS / 32], s_ns0[NTHREADS / 32];
    __shared__ float s_ps1[NTHREADS / 32], s_ns1[NTHREADS / 32];
    __shared__ float s_loss1;
    const int lane = tid & 31;
    const int wid = tid >> 5;
    if (lane == 0) {
        s_ps0[wid] = ps0; s_ns0[wid] = ns0;
        s_ps1[wid] = ps1; s_ns1[wid] = ns1;
    }
    __syncthreads();

    // Warp 1 finalizes row 1 into smem; warp 0 finalizes row 0, adds the
    // CTA's combined loss to device scratch, and the LAST CTA to finish
    // publishes out[0] and resets the scratch state for the next replay.
    if (tid == 32) {
        float ps = 0.0f, ns = 0.0f;
        #pragma unroll
        for (int w = 0; w < NTHREADS / 32; w++) { ps += s_ps1[w]; ns += s_ns1[w]; }
        s_loss1 = per_sample_loss(ps, ns, __ldg(&relation_ids[row1]));
    }
    __syncthreads();
    if (tid == 0) {
        float ps = 0.0f, ns = 0.0f;
        #pragma unroll
        for (int w = 0; w < NTHREADS / 32; w++) { ps += s_ps0[w]; ns += s_ns0[w]; }
        float loss = per_sample_loss(ps, ns, __ldg(&relation_ids[row0])) + s_loss1;
        atomicAdd(&g_scratch, loss);
        __threadfence();
        unsigned int ticket = atomicAdd(&g_ticket, 1u);
        if (ticket == gridDim.x - 1u) {
            // All CTAs' scratch adds are visible (fence before each ticket).
            out[0] = g_scratch * (1.0f / (float)B);
            g_scratch = 0.0f;   // reset for next graph replay
            g_ticket = 0u;
        }
    }
}

extern "C" void kernel_launch(void* const* d_in, const int* in_sizes, int n_in,
                              void* d_out, int out_size) {
    const float* h = (const float*)d_in[0];
    const float* t = (const float*)d_in[1];
    const float* r = (const float*)d_in[2];
    const int* relation_ids = (const int*)d_in[3];
    const int* neg_idx = (const int*)d_in[4];
    float* out = (float*)d_out;

    const int B = in_sizes[3];  // element count of relation_ids

    triplet_loss_kernel<<<B / ROWS_PER_CTA, NTHREADS>>>(h, t, r, relation_ids, neg_idx, out, B);
}

// round 9
// speedup vs baseline: 1.0473x; 1.0473x over previous
#include <cuda_runtime.h>
#include <cuda_bf16.h>

// BioTripletLoss: B=16384 rows, D=1024 fp32.
// pos = ||h+r-t||, neg = ||h+r-t[neg_idx]||
// dissim (rel==1): relu(0.6 - pos) + 0.5*exp(-pos)
// sim:             relu(pos - neg + 0.3) + 0.3*relu(0.1 - pos)
// out = mean over B.
//
// R9 = R7 kernel byte-identical (best: 2 rows/CTA, front-batched plain-global
// cache_hint loads, one atomic per CTA, regs 30, occ 90%, 31.5us) with the
// 1-thread zero_out kernel node replaced by a cudaMemsetAsync graph node
// (fixed-function path, cheaper than a kernel launch+retire).
// R8's fence-based single-kernel finalize REGRESSED (per-CTA MEMBAR.GPU
// cost > node overhead) and is abandoned.
// L2 policy: h, r -> evict_first (single-use); t -> evict_last (gather reuse,
// stays resident across graph replays).

#define DDIM 1024
#define NTHREADS 256
#define ROWS_PER_CTA 2

static constexpr float MARGIN = 0.3f;
static constexpr float MIN_POS_DIST = 0.1f;
static constexpr float PUSH_SCALE = 2.0f;

// Plain global-path 128-bit load with L2 eviction policy (no .nc).
__device__ __forceinline__ float4 ld_hint4(const float4* p, unsigned long long pol) {
    float4 v;
    asm("ld.global.L2::cache_hint.v4.f32 {%0,%1,%2,%3}, [%4], %5;"
        : "=f"(v.x), "=f"(v.y), "=f"(v.z), "=f"(v.w)
        : "l"(p), "l"(pol));
    return v;
}

__device__ __forceinline__ float per_sample_loss(float ps, float ns, int rel) {
    float pos_dist = sqrtf(ps);
    float neg_dist = sqrtf(ns);
    float loss;
    if (rel == 1) {
        loss = fmaxf(MARGIN * PUSH_SCALE - pos_dist, 0.0f) + 0.5f * expf(-pos_dist);
    } else {
        loss = fmaxf(pos_dist - neg_dist + MARGIN, 0.0f)
             + 0.3f * fmaxf(MIN_POS_DIST - pos_dist, 0.0f);
    }
    return loss;
}

__global__ __launch_bounds__(NTHREADS)
void triplet_loss_kernel(const float* __restrict__ h,
                         const float* __restrict__ t,
                         const float* __restrict__ r,
                         const int* __restrict__ relation_ids,
                         const int* __restrict__ neg_idx,
                         float* __restrict__ out,
                         int B) {
    const int row0 = blockIdx.x * ROWS_PER_CTA;
    const int row1 = row0 + 1;
    const int tid = threadIdx.x;

    unsigned long long pol_first, pol_last;
    asm("createpolicy.fractional.L2::evict_first.b64 %0, 1.0;" : "=l"(pol_first));
    asm("createpolicy.fractional.L2::evict_last.b64 %0, 1.0;"  : "=l"(pol_last));

    const int j0 = __ldg(&neg_idx[row0]);
    const int j1 = __ldg(&neg_idx[row1]);

    const float4* __restrict__ h4 = reinterpret_cast<const float4*>(h);
    const float4* __restrict__ r4 = reinterpret_cast<const float4*>(r);
    const float4* __restrict__ t4 = reinterpret_cast<const float4*>(t);
    const int V = DDIM / 4;  // 256 float4 per row == one per thread

    // Front-batch all 8 loads (MLP = 8).
    float4 hv0 = ld_hint4(h4 + (size_t)row0 * V + tid, pol_first);
    float4 rv0 = ld_hint4(r4 + (size_t)row0 * V + tid, pol_first);
    float4 tv0 = ld_hint4(t4 + (size_t)row0 * V + tid, pol_last);
    float4 nv0 = ld_hint4(t4 + (size_t)j0   * V + tid, pol_last);
    float4 hv1 = ld_hint4(h4 + (size_t)row1 * V + tid, pol_first);
    float4 rv1 = ld_hint4(r4 + (size_t)row1 * V + tid, pol_first);
    float4 tv1 = ld_hint4(t4 + (size_t)row1 * V + tid, pol_last);
    float4 nv1 = ld_hint4(t4 + (size_t)j1   * V + tid, pol_last);

    float hx, hy, hz, hw, d;

    // Row 0
    hx = hv0.x + rv0.x; hy = hv0.y + rv0.y; hz = hv0.z + rv0.z; hw = hv0.w + rv0.w;
    float ps0 = 0.0f, ns0 = 0.0f;
    d = hx - tv0.x; ps0 += d*d;  d = hy - tv0.y; ps0 += d*d;
    d = hz - tv0.z; ps0 += d*d;  d = hw - tv0.w; ps0 += d*d;
    d = hx - nv0.x; ns0 += d*d;  d = hy - nv0.y; ns0 += d*d;
    d = hz - nv0.z; ns0 += d*d;  d = hw - nv0.w; ns0 += d*d;

    // Row 1
    hx = hv1.x + rv1.x; hy = hv1.y + rv1.y; hz = hv1.z + rv1.z; hw = hv1.w + rv1.w;
    float ps1 = 0.0f, ns1 = 0.0f;
    d = hx - tv1.x; ps1 += d*d;  d = hy - tv1.y; ps1 += d*d;
    d = hz - tv1.z; ps1 += d*d;  d = hw - tv1.w; ps1 += d*d;
    d = hx - nv1.x; ns1 += d*d;  d = hy - nv1.y; ns1 += d*d;
    d = hz - nv1.z; ns1 += d*d;  d = hw - nv1.w; ns1 += d*d;

    // Warp reduce all four accumulators
    #pragma unroll
    for (int off = 16; off > 0; off >>= 1) {
        ps0 += __shfl_xor_sync(0xFFFFFFFFu, ps0, off);
        ns0 += __shfl_xor_sync(0xFFFFFFFFu, ns0, off);
        ps1 += __shfl_xor_sync(0xFFFFFFFFu, ps1, off);
        ns1 += __shfl_xor_sync(0xFFFFFFFFu, ns1, off);
    }

    // Block reduce across 8 warps, one barrier
    __shared__ float s_ps0[NTHREADS / 32], s_ns0[NTHREADS / 32];
    __shared__ float s_ps1[NTHREADS / 32], s_ns1[NTHREADS / 32];
    __shared__ float s_loss1;
    const int lane = tid & 31;
    const int wid = tid >> 5;
    if (lane == 0) {
        s_ps0[wid] = ps0; s_ns0[wid] = ns0;
        s_ps1[wid] = ps1; s_ns1[wid] = ns1;
    }
    __syncthreads();

    // Warp 1 finalizes row 1 into smem; warp 0 finalizes row 0 and issues the
    // CTA's single atomic after a second barrier.
    if (tid == 32) {
        float ps = 0.0f, ns = 0.0f;
        #pragma unroll
        for (int w = 0; w < NTHREADS / 32; w++) { ps += s_ps1[w]; ns += s_ns1[w]; }
        s_loss1 = per_sample_loss(ps, ns, __ldg(&relation_ids[row1]));
    }
    __syncthreads();
    if (tid == 0) {
        float ps = 0.0f, ns = 0.0f;
        #pragma unroll
        for (int w = 0; w < NTHREADS / 32; w++) { ps += s_ps0[w]; ns += s_ns0[w]; }
        float loss = per_sample_loss(ps, ns, __ldg(&relation_ids[row0])) + s_loss1;
        atomicAdd(out, loss * (1.0f / (float)B));
    }
}

extern "C" void kernel_launch(void* const* d_in, const int* in_sizes, int n_in,
                              void* d_out, int out_size) {
    const float* h = (const float*)d_in[0];
    const float* t = (const float*)d_in[1];
    const float* r = (const float*)d_in[2];
    const int* relation_ids = (const int*)d_in[3];
    const int* neg_idx = (const int*)d_in[4];
    float* out = (float*)d_out;

    const int B = in_sizes[3];  // element count of relation_ids

    // Zero the accumulator via a memset node (fixed-function path; cheaper
    // than a 1-thread kernel node). 0x00000000 == 0.0f.
    cudaMemsetAsync(out, 0, sizeof(float));
    triplet_loss_kernel<<<B / ROWS_PER_CTA, NTHREADS>>>(h, t, r, relation_ids, neg_idx, out, B);
}